// round 10
// baseline (speedup 1.0000x reference)
#include <cuda_runtime.h>
#include <cuda_bf16.h>
#include <cstdint>

// ---------------- problem constants ----------------
#define N_ROWS 131072
#define F_IN   256
#define N_SRC  32
#define F_OUT  64
#define W_COLS (N_SRC * F_OUT)   // 2048

#define BM 256
#define BK 32
#define CHUNKS (F_IN / BK)       // 8
#define NTHREADS 256
#define CAP 8192
#define TILES_PER_SRC (CAP / BM) // 32
#define GRID_GEMM (N_SRC * TILES_PER_SRC)  // 1024

// stage layout (per buffer):
//   A: 256 rows x 160B (32 fp32 + 8 pad floats) -> conflict-free LDS.64 frags
//   Bhi/Blo: 64 rows x 80B (32 bf16 + 8 pad)    -> conflict-free ldmatrix
#define ASB 160
#define SB  80
#define A_BYTES (BM * ASB)             // 40960
#define B_BYTES (F_OUT * SB)           // 5120
#define OFF_A   0
#define OFF_BHI A_BYTES
#define OFF_BLO (A_BYTES + B_BYTES)
#define STAGE_BYTES (A_BYTES + 2 * B_BYTES)   // 51200
#define SM_PERM 0
#define SM_STAGE 1024
#define SM_TOTAL (SM_STAGE + 2 * STAGE_BYTES) // 103424

// ---------------- device scratch ----------------
__device__ int g_cursor[N_SRC * 32];
__device__ int g_perm[N_SRC * CAP];
__device__ __nv_bfloat16 g_Whi[N_SRC * F_OUT * F_IN];  // [src][n][k]
__device__ __nv_bfloat16 g_Wlo[N_SRC * F_OUT * F_IN];

// ---------------- pass 0: reset cursors only ----------------
__global__ void k_init() {
    int i = threadIdx.x;
    if (i < N_SRC) g_cursor[i * 32] = i * CAP;
}

// ---------------- pass 1: scatter (warp-aggregated, ILP=4) ----------------
__global__ void k_scatter(const int* __restrict__ src) {
    int i0 = (blockIdx.x * blockDim.x + threadIdx.x) * 4;
    int4 s4 = *(const int4*)(src + i0);
    int sv[4] = { s4.x, s4.y, s4.z, s4.w };
    int lane = threadIdx.x & 31;
    #pragma unroll
    for (int j = 0; j < 4; j++) {
        int s = sv[j];
        unsigned m = __match_any_sync(0xffffffffu, s);
        int leader = __ffs(m) - 1;
        int rank = __popc(m & ((1u << lane) - 1));
        int base = 0;
        if (lane == leader) base = atomicAdd(&g_cursor[s * 32], __popc(m));
        base = __shfl_sync(0xffffffffu, base, leader);
        g_perm[base + rank] = i0 + j;
    }
}

// ---------------- pass 2: W -> [src][n][k] bf16 hi/lo ----------------
__global__ void k_prepW(const float* __restrict__ W) {
    __shared__ float tile[64][65];
    const int s = blockIdx.x >> 2;
    const int c = blockIdx.x & 3;
    const int tid = threadIdx.x;
    #pragma unroll
    for (int q = 0; q < 16; q++) {
        int idx = q * 256 + tid;
        int kk = idx >> 6, n = idx & 63;
        tile[kk][n] = W[(size_t)(c * 64 + kk) * W_COLS + s * F_OUT + n];
    }
    __syncthreads();
    #pragma unroll
    for (int q = 0; q < 16; q++) {
        int idx = q * 256 + tid;
        int n = idx >> 6, kk = idx & 63;
        float v = tile[kk][n];
        __nv_bfloat16 hi = __float2bfloat16(v);
        __nv_bfloat16 lo = __float2bfloat16(v - __bfloat162float(hi));
        size_t o = (size_t)(s * F_OUT + n) * F_IN + c * 64 + kk;
        g_Whi[o] = hi;
        g_Wlo[o] = lo;
    }
}

// ---------------- wrappers ----------------
__device__ __forceinline__ void mma_bf16(float* c, const uint32_t* a,
                                         uint32_t b0, uint32_t b1) {
    asm volatile(
        "mma.sync.aligned.m16n8k16.row.col.f32.bf16.bf16.f32 "
        "{%0,%1,%2,%3}, {%4,%5,%6,%7}, {%8,%9}, {%0,%1,%2,%3};"
        : "+f"(c[0]), "+f"(c[1]), "+f"(c[2]), "+f"(c[3])
        : "r"(a[0]), "r"(a[1]), "r"(a[2]), "r"(a[3]), "r"(b0), "r"(b1));
}
__device__ __forceinline__ void ldm_x4(uint32_t* r, uint32_t addr) {
    asm volatile("ldmatrix.sync.aligned.m8n8.x4.shared.b16 {%0,%1,%2,%3}, [%4];"
        : "=r"(r[0]), "=r"(r[1]), "=r"(r[2]), "=r"(r[3]) : "r"(addr));
}
__device__ __forceinline__ void cpa16(uint32_t dst, const void* src, int srcsz) {
    asm volatile("cp.async.ca.shared.global [%0], [%1], 16, %2;"
        :: "r"(dst), "l"(src), "r"(srcsz) : "memory");
}
__device__ __forceinline__ void cpa_commit() {
    asm volatile("cp.async.commit_group;" ::: "memory");
}
__device__ __forceinline__ void cvt_hl(float2 v, uint32_t& hi, uint32_t& lo) {
    __nv_bfloat162 h = __floats2bfloat162_rn(v.x, v.y);
    __nv_bfloat162 l = __floats2bfloat162_rn(v.x - __bfloat162float(h.x),
                                             v.y - __bfloat162float(h.y));
    hi = *(uint32_t*)&h;
    lo = *(uint32_t*)&l;
}

// ---------------- pass 3: cp.async double-buffered HMMA GEMM ----------------
// 256 threads / 8 warps; warp w computes rows w*32..w*32+31 x all 64 cols.
// A rows unique per warp (no duplicated LDS/cvt); B read by all warps but
// amortized over 256 rows.
__global__ void __launch_bounds__(NTHREADS, 2)
k_gemm(const float* __restrict__ x, const float* __restrict__ b,
       float* __restrict__ out) {
    extern __shared__ char smem[];
    const int tid = threadIdx.x;
    const int wid = tid >> 5;
    const int lid = tid & 31;
    const int g4 = lid >> 2;
    const int q4 = lid & 3;

    const int src   = blockIdx.x >> 5;
    const int local = blockIdx.x & (TILES_PER_SRC - 1);
    const int count = g_cursor[src * 32] - src * CAP;
    if (local * BM >= count) return;

    int* sperm = (int*)(smem + SM_PERM);
    sperm[tid] = g_perm[src * CAP + local * BM + tid];
    __syncthreads();

    const uint32_t smb = (uint32_t)__cvta_generic_to_shared(smem);
    const uint32_t stage0 = smb + SM_STAGE;
    char* const stage0g = smem + SM_STAGE;

    // A staging: 1 thread per row; 8 granules (full 128B chunk row)
    const bool avalid = (local * BM + tid) < count;
    const int aprow = avalid ? sperm[tid] : 0;
    const int asz = avalid ? 16 : 0;

    // B staging: 256 granules per split (64 rows x 4); exactly 1 per thread
    const int bn = tid >> 2;
    const int bg = tid & 3;

    auto issue = [&](int c, int buf) {
        const uint32_t bs = stage0 + buf * STAGE_BYTES;
        const char* gsrc = (const char*)(x + (size_t)aprow * F_IN + c * BK);
        const uint32_t adst = bs + OFF_A + tid * ASB;
        #pragma unroll
        for (int g = 0; g < 8; g++)
            cpa16(adst + g * 16, gsrc + g * 16, asz);
        {
            size_t gb = ((size_t)(src * F_OUT + bn) * F_IN + c * BK) * 2 + bg * 16;
            uint32_t dst = bs + bn * SB + bg * 16;
            cpa16(dst + OFF_BHI, (const char*)g_Whi + gb, 16);
            cpa16(dst + OFF_BLO, (const char*)g_Wlo + gb, 16);
        }
        cpa_commit();
    };

    float acc[2][8][4];   // [mb][p*2+nh][frag]
    #pragma unroll
    for (int mb = 0; mb < 2; mb++)
        #pragma unroll
        for (int nb = 0; nb < 8; nb++)
            #pragma unroll
            for (int j = 0; j < 4; j++) acc[mb][nb][j] = 0.0f;

    const uint32_t offB = ((lid & 7) + ((lid >> 4) & 1) * 8) * SB + ((lid >> 3) & 1) * 16;

    issue(0, 0);

    #pragma unroll 1
    for (int c = 0; c < CHUNKS; c++) {
        if (c + 1 < CHUNKS) {
            issue(c + 1, (c + 1) & 1);
            asm volatile("cp.async.wait_group 1;" ::: "memory");
        } else {
            asm volatile("cp.async.wait_group 0;" ::: "memory");
        }
        __syncthreads();

        const char* bufg = stage0g + (c & 1) * STAGE_BYTES;
        const uint32_t bsu = stage0 + (c & 1) * STAGE_BYTES;
        const uint32_t bHiB = bsu + OFF_BHI, bLoB = bsu + OFF_BLO;

        #pragma unroll
        for (int ks = 0; ks < 2; ks++) {
            // A fragments (2 m-blocks, unique rows per warp), converted in regs
            uint32_t ahi[2][4], alo[2][4];
            #pragma unroll
            for (int mb = 0; mb < 2; mb++) {
                const char* ab = bufg + OFF_A +
                    (uint32_t)(wid * 32 + mb * 16 + g4) * ASB + ks * 64 + q4 * 8;
                float2 f0 = *(const float2*)(ab);
                float2 f1 = *(const float2*)(ab + 8 * ASB);
                float2 f2 = *(const float2*)(ab + 32);
                float2 f3 = *(const float2*)(ab + 8 * ASB + 32);
                cvt_hl(f0, ahi[mb][0], alo[mb][0]);
                cvt_hl(f1, ahi[mb][1], alo[mb][1]);
                cvt_hl(f2, ahi[mb][2], alo[mb][2]);
                cvt_hl(f3, ahi[mb][3], alo[mb][3]);
            }
            #pragma unroll
            for (int p = 0; p < 4; p++) {
                uint32_t bo = (uint32_t)(p * 16) * SB + ks * 32 + offB;
                uint32_t bhi[4], blo[4];
                ldm_x4(bhi, bHiB + bo);
                ldm_x4(blo, bLoB + bo);
                #pragma unroll
                for (int mb = 0; mb < 2; mb++) {
                    mma_bf16(acc[mb][p * 2 + 0], ahi[mb], bhi[0], bhi[1]);
                    mma_bf16(acc[mb][p * 2 + 1], ahi[mb], bhi[2], bhi[3]);
                    mma_bf16(acc[mb][p * 2 + 0], ahi[mb], blo[0], blo[1]);
                    mma_bf16(acc[mb][p * 2 + 1], ahi[mb], blo[2], blo[3]);
                    mma_bf16(acc[mb][p * 2 + 0], alo[mb], bhi[0], bhi[1]);
                    mma_bf16(acc[mb][p * 2 + 1], alo[mb], bhi[2], bhi[3]);
                }
            }
        }
        __syncthreads();
    }

    // epilogue: bias + scattered store (count-based validity)
    #pragma unroll
    for (int p = 0; p < 4; p++) {
        #pragma unroll
        for (int nh = 0; nh < 2; nh++) {
            int col = p * 16 + nh * 8 + q4 * 2;
            float2 bv = *(const float2*)(b + src * F_OUT + col);
            #pragma unroll
            for (int mb = 0; mb < 2; mb++) {
                #pragma unroll
                for (int rh = 0; rh < 2; rh++) {
                    int r = wid * 32 + mb * 16 + g4 + rh * 8;
                    if (local * BM + r < count) {
                        int prow = sperm[r];
                        float2 o;
                        o.x = acc[mb][p * 2 + nh][rh * 2 + 0] + bv.x;
                        o.y = acc[mb][p * 2 + nh][rh * 2 + 1] + bv.y;
                        *(float2*)(out + (size_t)prow * F_OUT + col) = o;
                    }
                }
            }
        }
    }
}

// ---------------- launch ----------------
extern "C" void kernel_launch(void* const* d_in, const int* in_sizes, int n_in,
                              void* d_out, int out_size) {
    const float* x   = (const float*)d_in[0];
    const int*   src = (const int*)d_in[1];
    const float* W   = (const float*)d_in[2];
    const float* b   = (const float*)d_in[3];
    float* out = (float*)d_out;

    cudaFuncSetAttribute(k_gemm, cudaFuncAttributeMaxDynamicSharedMemorySize, SM_TOTAL);

    k_init<<<1, 32>>>();
    k_scatter<<<N_ROWS / (256 * 4), 256>>>(src);
    k_prepW<<<N_SRC * CHUNKS / 2, 256>>>(W);
    k_gemm<<<GRID_GEMM, NTHREADS, SM_TOTAL>>>(x, b, out);
}

// round 11
// speedup vs baseline: 2.0407x; 2.0407x over previous
#include <cuda_runtime.h>
#include <cuda_fp16.h>
#include <cstdint>

// ---------------- problem constants ----------------
#define N_ROWS 131072
#define F_IN   256
#define N_SRC  32
#define F_OUT  64
#define W_COLS (N_SRC * F_OUT)   // 2048

#define BM 128
#define BK 32
#define CHUNKS (F_IN / BK)       // 8
#define NTHREADS 256
#define CAP 8192
#define TILES_PER_SRC (CAP / BM) // 64
#define GRID_GEMM (N_SRC * TILES_PER_SRC)  // 2048

// stage layout (per buffer):
//   A: 128 rows x 160B (32 fp32 + 8 pad floats) -> conflict-free LDS.64 frags
//   B:  64 rows x 80B  (32 fp16 + 8 pad)        -> conflict-free ldmatrix
#define ASB 160
#define SB  80
#define A_BYTES (BM * ASB)             // 20480
#define B_BYTES (F_OUT * SB)           // 5120
#define OFF_A   0
#define OFF_B   A_BYTES
#define STAGE_BYTES (A_BYTES + B_BYTES)       // 25600
#define SM_PERM 0
#define SM_STAGE 512
#define SM_TOTAL (SM_STAGE + 2 * STAGE_BYTES) // 51712

// ---------------- device scratch ----------------
__device__ int g_cursor[N_SRC * 32];
__device__ int g_perm[N_SRC * CAP];
__device__ __half g_Wh[N_SRC * F_OUT * F_IN];   // [src][n][k], fp16

// ---------------- pass 0: reset cursors only ----------------
__global__ void k_init() {
    int i = threadIdx.x;
    if (i < N_SRC) g_cursor[i * 32] = i * CAP;
}

// ---------------- pass 1: scatter (warp-aggregated, ILP=4) ----------------
__global__ void k_scatter(const int* __restrict__ src) {
    int i0 = (blockIdx.x * blockDim.x + threadIdx.x) * 4;
    int4 s4 = *(const int4*)(src + i0);
    int sv[4] = { s4.x, s4.y, s4.z, s4.w };
    int lane = threadIdx.x & 31;
    #pragma unroll
    for (int j = 0; j < 4; j++) {
        int s = sv[j];
        unsigned m = __match_any_sync(0xffffffffu, s);
        int leader = __ffs(m) - 1;
        int rank = __popc(m & ((1u << lane) - 1));
        int base = 0;
        if (lane == leader) base = atomicAdd(&g_cursor[s * 32], __popc(m));
        base = __shfl_sync(0xffffffffu, base, leader);
        g_perm[base + rank] = i0 + j;
    }
}

// ---------------- pass 2: W -> [src][n][k] fp16 (smem transpose) ----------------
__global__ void k_prepW(const float* __restrict__ W) {
    __shared__ float tile[64][65];
    const int s = blockIdx.x >> 2;
    const int c = blockIdx.x & 3;
    const int tid = threadIdx.x;
    #pragma unroll
    for (int q = 0; q < 16; q++) {
        int idx = q * 256 + tid;
        int kk = idx >> 6, n = idx & 63;
        tile[kk][n] = W[(size_t)(c * 64 + kk) * W_COLS + s * F_OUT + n];
    }
    __syncthreads();
    #pragma unroll
    for (int q = 0; q < 16; q++) {
        int idx = q * 256 + tid;
        int n = idx >> 6, kk = idx & 63;
        size_t o = (size_t)(s * F_OUT + n) * F_IN + c * 64 + kk;
        g_Wh[o] = __float2half_rn(tile[kk][n]);
    }
}

// ---------------- wrappers ----------------
__device__ __forceinline__ void mma_f16(float* c, const uint32_t* a,
                                        uint32_t b0, uint32_t b1) {
    asm volatile(
        "mma.sync.aligned.m16n8k16.row.col.f32.f16.f16.f32 "
        "{%0,%1,%2,%3}, {%4,%5,%6,%7}, {%8,%9}, {%0,%1,%2,%3};"
        : "+f"(c[0]), "+f"(c[1]), "+f"(c[2]), "+f"(c[3])
        : "r"(a[0]), "r"(a[1]), "r"(a[2]), "r"(a[3]), "r"(b0), "r"(b1));
}
__device__ __forceinline__ void ldm_x4(uint32_t* r, uint32_t addr) {
    asm volatile("ldmatrix.sync.aligned.m8n8.x4.shared.b16 {%0,%1,%2,%3}, [%4];"
        : "=r"(r[0]), "=r"(r[1]), "=r"(r[2]), "=r"(r[3]) : "r"(addr));
}
__device__ __forceinline__ void cpa16(uint32_t dst, const void* src, int srcsz) {
    asm volatile("cp.async.ca.shared.global [%0], [%1], 16, %2;"
        :: "r"(dst), "l"(src), "r"(srcsz) : "memory");
}
__device__ __forceinline__ void cpa_commit() {
    asm volatile("cp.async.commit_group;" ::: "memory");
}
// fp32 pair -> fp16x2 hi + fp16x2 lo (residual); hi+lo recovers ~22 bits of x
__device__ __forceinline__ void cvt_hl(float2 v, uint32_t& hi, uint32_t& lo) {
    __half2 h = __floats2half2_rn(v.x, v.y);
    __half2 l = __floats2half2_rn(v.x - __half2float(h.x),
                                  v.y - __half2float(h.y));
    hi = *(uint32_t*)&h;
    lo = *(uint32_t*)&l;
}

// ---------------- pass 3: cp.async double-buffered HMMA GEMM ----------------
// 256 threads / 8 warps; warp w computes rows w*16..w*16+15 x all 64 cols.
// 2 split terms: x_hi*W + x_lo*W (W single fp16).
__global__ void __launch_bounds__(NTHREADS, 3)
k_gemm(const float* __restrict__ x, const float* __restrict__ b,
       float* __restrict__ out) {
    extern __shared__ char smem[];
    const int tid = threadIdx.x;
    const int wid = tid >> 5;
    const int lid = tid & 31;
    const int g4 = lid >> 2;
    const int q4 = lid & 3;

    const int src   = blockIdx.x >> 6;
    const int local = blockIdx.x & (TILES_PER_SRC - 1);
    const int count = g_cursor[src * 32] - src * CAP;
    if (local * BM >= count) return;

    int* sperm = (int*)(smem + SM_PERM);
    if (tid < BM) sperm[tid] = g_perm[src * CAP + local * BM + tid];
    __syncthreads();

    const uint32_t smb = (uint32_t)__cvta_generic_to_shared(smem);
    const uint32_t stage0 = smb + SM_STAGE;
    char* const stage0g = smem + SM_STAGE;

    // A staging: 2 threads per row; 4 granules each
    const int arow = tid >> 1;
    const int ahalf = tid & 1;
    const bool avalid = (local * BM + arow) < count;
    const int aprow = avalid ? sperm[arow] : 0;
    const int asz = avalid ? 16 : 0;

    // B staging: 256 granules (64 rows x 4); exactly 1 per thread
    const int bn = tid >> 2;
    const int bg = tid & 3;

    auto issue = [&](int c, int buf) {
        const uint32_t bs = stage0 + buf * STAGE_BYTES;
        const char* gsrc = (const char*)(x + (size_t)aprow * F_IN + c * BK) + ahalf * 64;
        const uint32_t adst = bs + OFF_A + arow * ASB + ahalf * 64;
        #pragma unroll
        for (int g = 0; g < 4; g++)
            cpa16(adst + g * 16, gsrc + g * 16, asz);
        {
            size_t gb = ((size_t)(src * F_OUT + bn) * F_IN + c * BK) * 2 + bg * 16;
            cpa16(bs + OFF_B + bn * SB + bg * 16, (const char*)g_Wh + gb, 16);
        }
        cpa_commit();
    };

    float acc[8][4];
    #pragma unroll
    for (int nb = 0; nb < 8; nb++)
        #pragma unroll
        for (int j = 0; j < 4; j++) acc[nb][j] = 0.0f;

    const uint32_t offB = ((lid & 7) + ((lid >> 4) & 1) * 8) * SB + ((lid >> 3) & 1) * 16;

    issue(0, 0);

    #pragma unroll 1
    for (int c = 0; c < CHUNKS; c++) {
        if (c + 1 < CHUNKS) {
            issue(c + 1, (c + 1) & 1);
            asm volatile("cp.async.wait_group 1;" ::: "memory");
        } else {
            asm volatile("cp.async.wait_group 0;" ::: "memory");
        }
        __syncthreads();

        const char* bufg = stage0g + (c & 1) * STAGE_BYTES;
        const uint32_t bB = stage0 + (c & 1) * STAGE_BYTES + OFF_B;

        #pragma unroll
        for (int ks = 0; ks < 2; ks++) {
            // A fragment (16 rows x k16) from fp32 smem -> fp16 hi/lo in regs
            uint32_t ahi[4], alo[4];
            {
                const char* ab = bufg + OFF_A +
                    (uint32_t)(wid * 16 + g4) * ASB + ks * 64 + q4 * 8;
                float2 f0 = *(const float2*)(ab);
                float2 f1 = *(const float2*)(ab + 8 * ASB);
                float2 f2 = *(const float2*)(ab + 32);
                float2 f3 = *(const float2*)(ab + 8 * ASB + 32);
                cvt_hl(f0, ahi[0], alo[0]);
                cvt_hl(f1, ahi[1], alo[1]);
                cvt_hl(f2, ahi[2], alo[2]);
                cvt_hl(f3, ahi[3], alo[3]);
            }
            #pragma unroll
            for (int p = 0; p < 4; p++) {
                uint32_t bo = (uint32_t)(p * 16) * SB + ks * 32 + offB;
                uint32_t bw[4];
                ldm_x4(bw, bB + bo);
                mma_f16(acc[p * 2 + 0], ahi, bw[0], bw[1]);
                mma_f16(acc[p * 2 + 1], ahi, bw[2], bw[3]);
                mma_f16(acc[p * 2 + 0], alo, bw[0], bw[1]);
                mma_f16(acc[p * 2 + 1], alo, bw[2], bw[3]);
            }
        }
        __syncthreads();
    }

    // epilogue: bias + scattered store (count-based validity)
    #pragma unroll
    for (int nb = 0; nb < 8; nb++) {
        int col = nb * 8 + q4 * 2;
        float2 bv = *(const float2*)(b + src * F_OUT + col);
        #pragma unroll
        for (int half = 0; half < 2; half++) {
            int r = wid * 16 + g4 + half * 8;
            if (local * BM + r < count) {
                int prow = sperm[r];
                float2 o;
                o.x = acc[nb][half * 2 + 0] + bv.x;
                o.y = acc[nb][half * 2 + 1] + bv.y;
                *(float2*)(out + (size_t)prow * F_OUT + col) = o;
            }
        }
    }
}

// ---------------- launch ----------------
extern "C" void kernel_launch(void* const* d_in, const int* in_sizes, int n_in,
                              void* d_out, int out_size) {
    const float* x   = (const float*)d_in[0];
    const int*   src = (const int*)d_in[1];
    const float* W   = (const float*)d_in[2];
    const float* b   = (const float*)d_in[3];
    float* out = (float*)d_out;

    cudaFuncSetAttribute(k_gemm, cudaFuncAttributeMaxDynamicSharedMemorySize, SM_TOTAL);

    k_init<<<1, 32>>>();
    k_scatter<<<N_ROWS / (256 * 4), 256>>>(src);
    k_prepW<<<N_SRC * CHUNKS / 2, 256>>>(W);
    k_gemm<<<GRID_GEMM, NTHREADS, SM_TOTAL>>>(x, b, out);
}